// round 15
// baseline (speedup 1.0000x reference)
#include <cuda_runtime.h>
#include <cuda_bf16.h>
#include <cstdint>
#include <cstddef>

#define Bdim 128
#define Sdim 512
#define Idim 256
#define Hdim 1024
#define NCTA 128

// scan decomposition: 16 N-blocks x 8 K-splits = 128 CTAs, 2 batch groups of 64
#define NK 8
#define NBLK 64    // N columns per CTA (scan)
#define KBLK 128   // K slice per CTA (scan)

// A-fragment staging (uint32 units): per (par, g, ks): 64 frags x 128
#define AF2_KS  (64 * 128)
#define AF2_G   (8 * AF2_KS)
#define AF2_PAR (2 * AF2_G)

// partials: [par][g][ks][64 rows][1024 cols]
#define PG   (8 * 64 * 1024)
#define PPAR (2 * PG)

// xproj smem: K-chunk 64, padded 144 B stride
#define AST2 144
#define XA_HI 0
#define XA_LO (XA_HI + 128 * AST2)
#define XB_HI (XA_LO + 128 * AST2)
#define XB_LO (XB_HI + 128 * AST2)
#define XSMEM_SZ (XB_LO + 128 * AST2)     // 73728 B

__device__ float g_P2[2 * PPAR];                  // 8 MB double-buffered partials
__device__ uint32_t g_Af2[2 * AF2_PAR];           // 1 MB fragment-layout staged h
__device__ unsigned g_grp[8 * 32];                // init/final grid barrier tree
__device__ unsigned g_root = 0;
__device__ unsigned g_gen = 0;
__device__ unsigned g_done2[16 * 32];             // per (g, ks) gemm-done counters
__device__ unsigned g_gst[16 * 32];               // per (g, ks) staged counters

// ---------------------------------------------------------------------------
// helpers
// ---------------------------------------------------------------------------
__device__ __forceinline__ unsigned ldv(const unsigned* p) {
    unsigned v;
    asm volatile("ld.volatile.global.u32 %0, [%1];" : "=r"(v) : "l"(p));
    return v;
}
__device__ __forceinline__ float2 ldcg2(const float* p) {
    return __ldcg(reinterpret_cast<const float2*>(p));
}
__device__ __forceinline__ float4 ldcg4(const float* p) {
    return __ldcg(reinterpret_cast<const float4*>(p));
}
__device__ __forceinline__ uint32_t smem_u32(const void* p) {
    uint32_t a;
    asm("{ .reg .u64 t; cvta.to.shared.u64 t, %1; cvt.u32.u64 %0, t; }" : "=r"(a) : "l"(p));
    return a;
}

#define LDSM4(r, addr) \
    asm volatile("ldmatrix.sync.aligned.m8n8.x4.shared.b16 {%0,%1,%2,%3}, [%4];" \
        : "=r"((r)[0]), "=r"((r)[1]), "=r"((r)[2]), "=r"((r)[3]) : "r"(addr))

#define MMA_BF16(d, a, b) \
    asm volatile("mma.sync.aligned.m16n8k16.row.col.f32.bf16.bf16.f32 " \
        "{%0,%1,%2,%3}, {%4,%5,%6,%7}, {%8,%9}, {%0,%1,%2,%3};" \
        : "+f"((d)[0]), "+f"((d)[1]), "+f"((d)[2]), "+f"((d)[3]) \
        : "r"((a)[0]), "r"((a)[1]), "r"((a)[2]), "r"((a)[3]), \
          "r"((b)[0]), "r"((b)[1]))

#define LDCG128(r, p) do { \
    uint4 v_ = __ldcg(reinterpret_cast<const uint4*>(p)); \
    (r)[0] = v_.x; (r)[1] = v_.y; (r)[2] = v_.z; (r)[3] = v_.w; } while (0)

__device__ __forceinline__ void split4(float4 v, uint2& uh, uint2& ul) {
    __nv_bfloat16 h0 = __float2bfloat16(v.x);
    __nv_bfloat16 h1 = __float2bfloat16(v.y);
    __nv_bfloat16 h2 = __float2bfloat16(v.z);
    __nv_bfloat16 h3 = __float2bfloat16(v.w);
    __nv_bfloat16 l0 = __float2bfloat16(v.x - __bfloat162float(h0));
    __nv_bfloat16 l1 = __float2bfloat16(v.y - __bfloat162float(h1));
    __nv_bfloat16 l2 = __float2bfloat16(v.z - __bfloat162float(h2));
    __nv_bfloat16 l3 = __float2bfloat16(v.w - __bfloat162float(h3));
    uh.x = (uint32_t)__bfloat16_as_ushort(h0) | ((uint32_t)__bfloat16_as_ushort(h1) << 16);
    uh.y = (uint32_t)__bfloat16_as_ushort(h2) | ((uint32_t)__bfloat16_as_ushort(h3) << 16);
    ul.x = (uint32_t)__bfloat16_as_ushort(l0) | ((uint32_t)__bfloat16_as_ushort(l1) << 16);
    ul.y = (uint32_t)__bfloat16_as_ushort(l2) | ((uint32_t)__bfloat16_as_ushort(l3) << 16);
}
__device__ __forceinline__ void split2(float2 v, uint32_t& uh, uint32_t& ul) {
    __nv_bfloat16 h0 = __float2bfloat16(v.x);
    __nv_bfloat16 h1 = __float2bfloat16(v.y);
    __nv_bfloat16 l0 = __float2bfloat16(v.x - __bfloat162float(h0));
    __nv_bfloat16 l1 = __float2bfloat16(v.y - __bfloat162float(h1));
    uh = (uint32_t)__bfloat16_as_ushort(h0) | ((uint32_t)__bfloat16_as_ushort(h1) << 16);
    ul = (uint32_t)__bfloat16_as_ushort(l0) | ((uint32_t)__bfloat16_as_ushort(l1) << 16);
}

__device__ __forceinline__ float tanh_fast(float x) {
    float xc = fminf(fmaxf(x, -9.0f), 9.0f);
    float e = __expf(2.0f * xc);
    return __fdividef(e - 1.0f, e + 1.0f);
}

// Full-grid two-level tree barrier (init/final only; monotonic, replay-safe).
__device__ __forceinline__ void grid_barrier() {
    __threadfence();
    __syncthreads();
    if (threadIdx.x == 0) {
        unsigned my = ldv(&g_gen);
        unsigned o = atomicAdd(&g_grp[(blockIdx.x & 7) * 32], 1u);
        if ((o & 15u) == 15u) {
            unsigned r = atomicAdd(&g_root, 1u);
            if ((r & 7u) == 7u) atomicAdd(&g_gen, 1u);
        }
        while (ldv(&g_gen) == my) { }
    }
    __syncthreads();
}

// Stage one (hi, lo) column-pair of h (within-group row 0..63) in fragment layout.
__device__ __forceinline__ void stage_pair2(int g, int ks, int par, int row, int c,
                                            uint32_t uh, uint32_t ul) {
    int wr = row >> 5;          // 0..1
    int mt = (row >> 4) & 1;
    int fr = row & 15;
    int kt = c >> 4;
    int fk = c & 15;
    int p  = (fr >> 3) + ((fk >> 3) << 1);
    int lane = (fr & 7) * 4 + ((fk & 7) >> 1);
    int fi = (wr * 8 + kt) * 4 + mt;
    uint32_t* b = g_Af2 + (size_t)par * AF2_PAR + (size_t)g * AF2_G
                + (size_t)ks * AF2_KS + lane * 4 + p;
    b[(size_t)fi * 128]       = uh;
    b[(size_t)(fi + 2) * 128] = ul;
}

// ---------------------------------------------------------------------------
// Phase 1: x_proj via bf16 hi/lo mma.sync (unchanged — known good)
// ---------------------------------------------------------------------------
__global__ __launch_bounds__(256) void xproj_kernel(
    const float* __restrict__ X,
    const float* __restrict__ W_ih,
    const float* __restrict__ b_ih,
    const float* __restrict__ b_hh,
    float* __restrict__ hs)
{
    extern __shared__ char xsm[];
    const uint32_t sbase = smem_u32(xsm);
    const int nb = blockIdx.x;
    const int s  = blockIdx.y;
    const int tid = threadIdx.x;
    const int wid = tid >> 5;
    const int lid = tid & 31;

    const int wm = (wid & 3) * 32;
    const int wn = (wid >> 2) * 64;

    const uint32_t aRow = (uint32_t)(wm + (lid & 15));
    const uint32_t aCol = (uint32_t)((lid >> 4) * 8);
    const uint32_t aHiB = sbase + XA_HI + aRow * AST2 + aCol * 2;
    const uint32_t aLoB = aHiB + (XA_LO - XA_HI);
    const uint32_t bRow = (uint32_t)(wn + ((lid >> 4) << 3) + (lid & 7));
    const uint32_t bCol = (uint32_t)(((lid >> 3) & 1) * 8);
    const uint32_t bHiB = sbase + XB_HI + bRow * AST2 + bCol * 2;
    const uint32_t bLoB = bHiB + (XB_LO - XB_HI);

    float acc[2][8][4];
    #pragma unroll
    for (int mt = 0; mt < 2; mt++)
        #pragma unroll
        for (int nf = 0; nf < 8; nf++)
            #pragma unroll
            for (int r = 0; r < 4; r++) acc[mt][nf][r] = 0.0f;

    for (int c = 0; c < 4; c++) {
        const int kc = c * 64;
        #pragma unroll
        for (int i = 0; i < 8; i++) {
            int u = tid + i * 256;
            int m  = u >> 4;
            int c4 = u & 15;
            float4 v = *reinterpret_cast<const float4*>(
                X + ((size_t)m * Sdim + s) * Idim + kc + c4 * 4);
            uint2 uh, ul;
            split4(v, uh, ul);
            *reinterpret_cast<uint2*>(xsm + XA_HI + m * AST2 + c4 * 8) = uh;
            *reinterpret_cast<uint2*>(xsm + XA_LO + m * AST2 + c4 * 8) = ul;
        }
        #pragma unroll
        for (int i = 0; i < 8; i++) {
            int u = tid + i * 256;
            int n  = u >> 4;
            int c4 = u & 15;
            float4 v = *reinterpret_cast<const float4*>(
                W_ih + (size_t)(nb * 128 + n) * Idim + kc + c4 * 4);
            uint2 uh, ul;
            split4(v, uh, ul);
            *reinterpret_cast<uint2*>(xsm + XB_HI + n * AST2 + c4 * 8) = uh;
            *reinterpret_cast<uint2*>(xsm + XB_LO + n * AST2 + c4 * 8) = ul;
        }
        __syncthreads();

        #pragma unroll
        for (int kt = 0; kt < 4; kt++) {
            const uint32_t ko = (uint32_t)(kt * 32);
            uint32_t ah[2][4], al[2][4];
            LDSM4(ah[0], aHiB + ko);
            LDSM4(ah[1], aHiB + 16 * AST2 + ko);
            LDSM4(al[0], aLoB + ko);
            LDSM4(al[1], aLoB + 16 * AST2 + ko);
            #pragma unroll
            for (int np = 0; np < 4; np++) {
                uint32_t bh[4], bl[4];
                LDSM4(bh, bHiB + np * (16 * AST2) + ko);
                LDSM4(bl, bLoB + np * (16 * AST2) + ko);
                #pragma unroll
                for (int mt = 0; mt < 2; mt++) {
                    MMA_BF16(acc[mt][np * 2 + 0], ah[mt], bh + 0);
                    MMA_BF16(acc[mt][np * 2 + 0], ah[mt], bl + 0);
                    MMA_BF16(acc[mt][np * 2 + 0], al[mt], bh + 0);
                    MMA_BF16(acc[mt][np * 2 + 1], ah[mt], bh + 2);
                    MMA_BF16(acc[mt][np * 2 + 1], ah[mt], bl + 2);
                    MMA_BF16(acc[mt][np * 2 + 1], al[mt], bh + 2);
                }
            }
        }
        __syncthreads();
    }

    #pragma unroll
    for (int mt = 0; mt < 2; mt++) {
        const int row = wm + mt * 16 + (lid >> 2);
        #pragma unroll
        for (int nf = 0; nf < 8; nf++) {
            const int col = nb * 128 + wn + nf * 8 + (lid & 3) * 2;
            const float bb0 = __ldg(b_ih + col) + __ldg(b_hh + col);
            const float bb1 = __ldg(b_ih + col + 1) + __ldg(b_hh + col + 1);
            float* o = hs + ((size_t)s * Bdim + row) * Hdim + col;
            *reinterpret_cast<float2*>(o) =
                make_float2(acc[mt][nf][0] + bb0, acc[mt][nf][1] + bb1);
            *reinterpret_cast<float2*>(o + 8 * Hdim) =
                make_float2(acc[mt][nf][2] + bb0, acc[mt][nf][3] + bb1);
        }
    }
}

// ---------------------------------------------------------------------------
// Phase 2: persistent scan, 2 batch groups of 64 rows pipelined to hide sync.
// CTA (nb, ks): per group g: gemm M=64 N=64 K=128 (B in regs, A frags via LDG)
//   -> partials -> signal done[g][nb>>1]
// then per group g: wait done[g][ks] -> reduce rows nb*4..+4 x cols ks*128..+128
//   -> tanh -> stage fragments -> signal gst[g][ks]
// gemm at t>0 waits gst[g][ks] >= 16*t (hidden behind the other group's work).
// ---------------------------------------------------------------------------
__global__ __launch_bounds__(256, 1) void rnn_scan_kernel(
    const float* __restrict__ hidden,
    const float* __restrict__ W_hh,
    const float* __restrict__ W_fc,
    const float* __restrict__ b_fc,
    float* __restrict__ out,
    float* __restrict__ hs,
    float* __restrict__ ss,
    float* __restrict__ sf)
{
    const int tid = threadIdx.x;
    const int wid = tid >> 5;
    const int lid = tid & 31;
    const int cta = blockIdx.x;
    const int nb  = cta >> 3;     // 0..15 N-block
    const int ks  = cta & 7;      // 0..7  K-split
    const int k0  = ks * KBLK;

    // warp layout: 2(m) x 4(n)
    const int wr = wid & 1;          // rows wr*32..+31 (within 64-row group)
    const int wn = wid >> 1;         // 0..3: cols wn*16..+15 (of CTA's n64)

    // ---- one-time: hoist B (W_hh) fragments into registers (hi/lo) ----
    uint32_t bh[8][2][2], bl[8][2][2];
    #pragma unroll
    for (int kt = 0; kt < 8; kt++) {
        #pragma unroll
        for (int nt = 0; nt < 2; nt++) {
            int n_g = nb * NBLK + wn * 16 + nt * 8 + (lid >> 2);
            int k_g = k0 + kt * 16 + (lid & 3) * 2;
            const float* wp = W_hh + (size_t)n_g * Hdim + k_g;
            float2 w0 = *reinterpret_cast<const float2*>(wp);
            float2 w1 = *reinterpret_cast<const float2*>(wp + 8);
            split2(w0, bh[kt][nt][0], bl[kt][nt][0]);
            split2(w1, bh[kt][nt][1], bl[kt][nt][1]);
        }
    }

    // ---- one-time: stage h0 (both groups, this CTA's reduce rows) at par 0 ----
    #pragma unroll
    for (int e = 0; e < 2; e++) {
        int idx = tid * 2 + e;        // 0..511
        int g   = idx >> 8;
        int rem = idx & 255;
        int rl  = rem >> 6;           // 0..3
        int c   = (rem & 63) * 2;     // 0..126
        int grow = nb * 4 + rl;       // within-group row
        int growg = g * 64 + grow;    // global batch row
        float2 v = *reinterpret_cast<const float2*>(
            hidden + (size_t)growg * Hdim + k0 + c);
        uint32_t uh, ul;
        split2(v, uh, ul);
        stage_pair2(g, ks, 0, grow, c, uh, ul);
    }

    // counter bases (monotonic counters; replay-safe)
    unsigned db[2] = {0, 0}, gb[2] = {0, 0};
    if (tid == 0) {
        db[0] = ldv(&g_done2[(0 * 8 + ks) * 32]);
        db[1] = ldv(&g_done2[(1 * 8 + ks) * 32]);
        gb[0] = ldv(&g_gst[(0 * 8 + ks) * 32]);
        gb[1] = ldv(&g_gst[(1 * 8 + ks) * 32]);
    }
    grid_barrier();

    for (int t = 0; t < Sdim; t++) {
        const int par = t & 1;

        // ================= GEMM phase (both groups) =================
        #pragma unroll
        for (int g = 0; g < 2; g++) {
            if (t > 0) {
                if (tid == 0) {
                    unsigned need = gb[g] + 16u * (unsigned)t;
                    while ((int)(ldv(&g_gst[(g * 8 + ks) * 32]) - need) < 0) { }
                }
                __syncthreads();
            }

            const uint32_t* afb = g_Af2 + (size_t)par * AF2_PAR + (size_t)g * AF2_G
                                + (size_t)ks * AF2_KS + lid * 4;

            float acc[2][2][4];
            #pragma unroll
            for (int mt = 0; mt < 2; mt++)
                #pragma unroll
                for (int nt = 0; nt < 2; nt++)
                    #pragma unroll
                    for (int r = 0; r < 4; r++) acc[mt][nt][r] = 0.0f;

            uint32_t ah[2][2][4], al[2][2][4];
            {
                const uint32_t* fb = afb + (size_t)(wr * 8) * 512;
                LDCG128(ah[0][0], fb);
                LDCG128(ah[0][1], fb + 128);
                LDCG128(al[0][0], fb + 256);
                LDCG128(al[0][1], fb + 384);
            }
            #pragma unroll
            for (int kt = 0; kt < 8; kt++) {
                const int cur = kt & 1, nxt = cur ^ 1;
                if (kt < 7) {
                    const uint32_t* fb = afb + (size_t)(wr * 8 + kt + 1) * 512;
                    LDCG128(ah[nxt][0], fb);
                    LDCG128(ah[nxt][1], fb + 128);
                    LDCG128(al[nxt][0], fb + 256);
                    LDCG128(al[nxt][1], fb + 384);
                }
                #pragma unroll
                for (int mt = 0; mt < 2; mt++) {
                    #pragma unroll
                    for (int nt = 0; nt < 2; nt++) {
                        MMA_BF16(acc[mt][nt], ah[cur][mt], bh[kt][nt]);
                        MMA_BF16(acc[mt][nt], ah[cur][mt], bl[kt][nt]);
                        MMA_BF16(acc[mt][nt], al[cur][mt], bh[kt][nt]);
                    }
                }
            }

            // partials: P2[par][g][ks][row][col]
            float* Pg = g_P2 + (size_t)par * PPAR + (size_t)g * PG + (size_t)ks * (64 * 1024);
            #pragma unroll
            for (int mt = 0; mt < 2; mt++) {
                #pragma unroll
                for (int nt = 0; nt < 2; nt++) {
                    const int row = wr * 32 + mt * 16 + (lid >> 2);
                    const int col = nb * NBLK + wn * 16 + nt * 8 + (lid & 3) * 2;
                    float* p = Pg + (size_t)row * 1024 + col;
                    *reinterpret_cast<float2*>(p) =
                        make_float2(acc[mt][nt][0], acc[mt][nt][1]);
                    *reinterpret_cast<float2*>(p + 8 * 1024) =
                        make_float2(acc[mt][nt][2], acc[mt][nt][3]);
                }
            }

            __threadfence();
            __syncthreads();
            if (tid == 0) atomicAdd(&g_done2[(g * 8 + (nb >> 1)) * 32], 1u);
        }

        // ================= reduce phase (both groups) =================
        #pragma unroll
        for (int g = 0; g < 2; g++) {
            if (tid == 0) {
                unsigned need = db[g] + 16u * (unsigned)(t + 1);
                while ((int)(ldv(&g_done2[(g * 8 + ks) * 32]) - need) < 0) { }
            }
            __syncthreads();

            const int rl = tid >> 6;            // 0..3
            const int c  = (tid & 63) * 2;      // 0..126 (slice-local)
            const int grow = nb * 4 + rl;       // within-group row
            const int growg = g * 64 + grow;    // global row
            const size_t colH = (size_t)k0 + c;

            float* xp = hs + (size_t)t * Bdim * Hdim + (size_t)growg * Hdim + colH;
            float2 sum = *reinterpret_cast<const float2*>(xp);
            const float* Pb = g_P2 + (size_t)par * PPAR + (size_t)g * PG;
            #pragma unroll
            for (int q = 0; q < NK; q++) {
                float2 pv = ldcg2(Pb + (size_t)q * (64 * 1024) + (size_t)grow * 1024 + colH);
                sum.x += pv.x; sum.y += pv.y;
            }
            float2 hv = make_float2(tanh_fast(sum.x), tanh_fast(sum.y));
            *reinterpret_cast<float2*>(xp) = hv;

            uint32_t uh, ul;
            split2(hv, uh, ul);
            stage_pair2(g, ks, (t + 1) & 1, grow, c, uh, ul);

            __threadfence();
            __syncthreads();
            if (tid == 0) atomicAdd(&g_gst[(g * 8 + ks) * 32], 1u);
        }
    }

    grid_barrier();   // all hs rows final before cross-row tail reads

    // ---- tail: state_start, state_final, fc output ----
    const float* hfin = hs + (size_t)(Sdim - 1) * Bdim * Hdim;
    {
        const size_t off = (size_t)cta * Hdim + tid * 4;
        *reinterpret_cast<float4*>(ss + off) = ldcg4(hs + off);
        *reinterpret_cast<float4*>(sf + off) = ldcg4(hfin + off);
    }
    if (cta < 16) {
        const int w = tid >> 5;
        const int lane = tid & 31;
        const int b = cta * 8 + w;
        float sum = 0.0f;
        #pragma unroll 8
        for (int h = lane; h < Hdim; h += 32)
            sum += __ldcg(hfin + (size_t)b * Hdim + h) * W_fc[h];
        #pragma unroll
        for (int o = 16; o > 0; o >>= 1)
            sum += __shfl_down_sync(0xffffffffu, sum, o);
        if (lane == 0) out[b] = sum + b_fc[0];
    }
}

extern "C" void kernel_launch(void* const* d_in, const int* in_sizes, int n_in,
                              void* d_out, int out_size) {
    (void)in_sizes; (void)n_in; (void)out_size;
    const float* X      = (const float*)d_in[0];
    const float* hidden = (const float*)d_in[1];
    const float* W_ih   = (const float*)d_in[2];
    const float* W_hh   = (const float*)d_in[3];
    const float* b_ih   = (const float*)d_in[4];
    const float* b_hh   = (const float*)d_in[5];
    const float* W_fc   = (const float*)d_in[6];
    const float* b_fc   = (const float*)d_in[7];

    float* out = (float*)d_out;                       // (B, 1)
    float* hs  = out + Bdim;                          // (S, B, H)
    float* ss  = hs + (size_t)Sdim * Bdim * Hdim;     // state_start (B,H)
    float* sf  = ss + (size_t)Bdim * Hdim;            // state_final (B,H)

    cudaFuncSetAttribute(xproj_kernel,
                         cudaFuncAttributeMaxDynamicSharedMemorySize, XSMEM_SZ);

    xproj_kernel<<<dim3(8, Sdim), 256, XSMEM_SZ>>>(X, W_ih, b_ih, b_hh, hs);
    rnn_scan_kernel<<<NCTA, 256>>>(hidden, W_hh, W_fc, b_fc, out, hs, ss, sf);
}

// round 16
// speedup vs baseline: 1.0140x; 1.0140x over previous
#include <cuda_runtime.h>
#include <cuda_bf16.h>
#include <cstdint>
#include <cstddef>

#define Bdim 128
#define Sdim 512
#define Idim 256
#define Hdim 1024
#define NCTA 128

// scan decomposition: 16 N-blocks x 8 K-splits = 128 CTAs
#define NK 8
#define NBLK 64    // N columns per CTA (scan)
#define KBLK 128   // K slice per CTA (scan)

// A-fragment staging buffer geometry (uint32 units)
// frag id fi = (wr*8 + kt)*4 + prec*2 + mt ; per ks: 4*8*4 = 128 frags x 128 uints
#define AF_KS  (128 * 128)
#define AF_PAR (8 * AF_KS)

// xproj smem: K-chunk 64, padded 144 B stride
#define AST2 144
#define XA_HI 0
#define XA_LO (XA_HI + 128 * AST2)
#define XB_HI (XA_LO + 128 * AST2)
#define XB_LO (XB_HI + 128 * AST2)
#define XSMEM_SZ (XB_LO + 128 * AST2)     // 73728 B

__device__ float g_P[2 * NK * Bdim * Hdim];       // double-buffered split-K partials (8 MB)
__device__ uint32_t g_Af[2 * AF_PAR];             // fragment-layout staged A (hi/lo pairs), 1 MB
__device__ unsigned g_grp[8 * 32];                // init/final grid barrier tree
__device__ unsigned g_root = 0;
__device__ unsigned g_gen = 0;
__device__ unsigned g_done[8 * 32];               // per-ks gemm-done counters (monotonic)
__device__ unsigned g_gst[8 * 32];                // per-ks staged counters (monotonic)

// ---------------------------------------------------------------------------
// helpers
// ---------------------------------------------------------------------------
__device__ __forceinline__ unsigned ldv(const unsigned* p) {
    unsigned v;
    asm volatile("ld.volatile.global.u32 %0, [%1];" : "=r"(v) : "l"(p));
    return v;
}
__device__ __forceinline__ unsigned ldrelax(const unsigned* p) {
    unsigned v;
    asm volatile("ld.relaxed.gpu.global.u32 %0, [%1];" : "=r"(v) : "l"(p));
    return v;
}
__device__ __forceinline__ void red_release(unsigned* p, unsigned v) {
    asm volatile("red.release.gpu.global.add.u32 [%0], %1;" :: "l"(p), "r"(v) : "memory");
}
__device__ __forceinline__ void fence_acq() {
    asm volatile("fence.acq_rel.gpu;" ::: "memory");
}
__device__ __forceinline__ float2 ldcg2(const float* p) {
    return __ldcg(reinterpret_cast<const float2*>(p));
}
__device__ __forceinline__ float4 ldcg4(const float* p) {
    return __ldcg(reinterpret_cast<const float4*>(p));
}
__device__ __forceinline__ uint32_t smem_u32(const void* p) {
    uint32_t a;
    asm("{ .reg .u64 t; cvta.to.shared.u64 t, %1; cvt.u32.u64 %0, t; }" : "=r"(a) : "l"(p));
    return a;
}

#define LDSM4(r, addr) \
    asm volatile("ldmatrix.sync.aligned.m8n8.x4.shared.b16 {%0,%1,%2,%3}, [%4];" \
        : "=r"((r)[0]), "=r"((r)[1]), "=r"((r)[2]), "=r"((r)[3]) : "r"(addr))

#define MMA_BF16(d, a, b) \
    asm volatile("mma.sync.aligned.m16n8k16.row.col.f32.bf16.bf16.f32 " \
        "{%0,%1,%2,%3}, {%4,%5,%6,%7}, {%8,%9}, {%0,%1,%2,%3};" \
        : "+f"((d)[0]), "+f"((d)[1]), "+f"((d)[2]), "+f"((d)[3]) \
        : "r"((a)[0]), "r"((a)[1]), "r"((a)[2]), "r"((a)[3]), \
          "r"((b)[0]), "r"((b)[1]))

#define LDCG128(r, p) do { \
    uint4 v_ = __ldcg(reinterpret_cast<const uint4*>(p)); \
    (r)[0] = v_.x; (r)[1] = v_.y; (r)[2] = v_.z; (r)[3] = v_.w; } while (0)

__device__ __forceinline__ void split4(float4 v, uint2& uh, uint2& ul) {
    __nv_bfloat16 h0 = __float2bfloat16(v.x);
    __nv_bfloat16 h1 = __float2bfloat16(v.y);
    __nv_bfloat16 h2 = __float2bfloat16(v.z);
    __nv_bfloat16 h3 = __float2bfloat16(v.w);
    __nv_bfloat16 l0 = __float2bfloat16(v.x - __bfloat162float(h0));
    __nv_bfloat16 l1 = __float2bfloat16(v.y - __bfloat162float(h1));
    __nv_bfloat16 l2 = __float2bfloat16(v.z - __bfloat162float(h2));
    __nv_bfloat16 l3 = __float2bfloat16(v.w - __bfloat162float(h3));
    uh.x = (uint32_t)__bfloat16_as_ushort(h0) | ((uint32_t)__bfloat16_as_ushort(h1) << 16);
    uh.y = (uint32_t)__bfloat16_as_ushort(h2) | ((uint32_t)__bfloat16_as_ushort(h3) << 16);
    ul.x = (uint32_t)__bfloat16_as_ushort(l0) | ((uint32_t)__bfloat16_as_ushort(l1) << 16);
    ul.y = (uint32_t)__bfloat16_as_ushort(l2) | ((uint32_t)__bfloat16_as_ushort(l3) << 16);
}
__device__ __forceinline__ void split2(float2 v, uint32_t& uh, uint32_t& ul) {
    __nv_bfloat16 h0 = __float2bfloat16(v.x);
    __nv_bfloat16 h1 = __float2bfloat16(v.y);
    __nv_bfloat16 l0 = __float2bfloat16(v.x - __bfloat162float(h0));
    __nv_bfloat16 l1 = __float2bfloat16(v.y - __bfloat162float(h1));
    uh = (uint32_t)__bfloat16_as_ushort(h0) | ((uint32_t)__bfloat16_as_ushort(h1) << 16);
    ul = (uint32_t)__bfloat16_as_ushort(l0) | ((uint32_t)__bfloat16_as_ushort(l1) << 16);
}

__device__ __forceinline__ float tanh_fast(float x) {
    float xc = fminf(fmaxf(x, -9.0f), 9.0f);
    float e = __expf(2.0f * xc);
    return __fdividef(e - 1.0f, e + 1.0f);
}

// Full-grid two-level tree barrier (init/final only; monotonic, replay-safe).
__device__ __forceinline__ void grid_barrier() {
    __threadfence();
    __syncthreads();
    if (threadIdx.x == 0) {
        unsigned my = ldv(&g_gen);
        unsigned o = atomicAdd(&g_grp[(blockIdx.x & 7) * 32], 1u);
        if ((o & 15u) == 15u) {
            unsigned r = atomicAdd(&g_root, 1u);
            if ((r & 7u) == 7u) atomicAdd(&g_gen, 1u);
        }
        while (ldv(&g_gen) == my) { }
    }
    __syncthreads();
}

// Write one (hi, lo) column-pair of h into the fragment-layout staging buffer.
// Mirrors the mma.sync m16n8k16 A-fragment mapping.
__device__ __forceinline__ void stage_pair(int ks, int par, int row, int c,
                                           uint32_t uh, uint32_t ul) {
    int wr = row >> 5;
    int mt = (row >> 4) & 1;
    int fr = row & 15;
    int kt = c >> 4;
    int fk = c & 15;
    int p  = (fr >> 3) + ((fk >> 3) << 1);
    int lane = (fr & 7) * 4 + ((fk & 7) >> 1);
    int fiH = (wr * 8 + kt) * 4 + mt;        // prec 0
    uint32_t* b = g_Af + (size_t)par * AF_PAR + ks * AF_KS + lane * 4 + p;
    b[(size_t)fiH * 128]       = uh;
    b[(size_t)(fiH + 2) * 128] = ul;          // prec 1
}

// ---------------------------------------------------------------------------
// Phase 1: x_proj via bf16 hi/lo mma.sync (unchanged — known good)
// ---------------------------------------------------------------------------
__global__ __launch_bounds__(256) void xproj_kernel(
    const float* __restrict__ X,
    const float* __restrict__ W_ih,
    const float* __restrict__ b_ih,
    const float* __restrict__ b_hh,
    float* __restrict__ hs)
{
    extern __shared__ char xsm[];
    const uint32_t sbase = smem_u32(xsm);
    const int nb = blockIdx.x;
    const int s  = blockIdx.y;
    const int tid = threadIdx.x;
    const int wid = tid >> 5;
    const int lid = tid & 31;

    const int wm = (wid & 3) * 32;
    const int wn = (wid >> 2) * 64;

    const uint32_t aRow = (uint32_t)(wm + (lid & 15));
    const uint32_t aCol = (uint32_t)((lid >> 4) * 8);
    const uint32_t aHiB = sbase + XA_HI + aRow * AST2 + aCol * 2;
    const uint32_t aLoB = aHiB + (XA_LO - XA_HI);
    const uint32_t bRow = (uint32_t)(wn + ((lid >> 4) << 3) + (lid & 7));
    const uint32_t bCol = (uint32_t)(((lid >> 3) & 1) * 8);
    const uint32_t bHiB = sbase + XB_HI + bRow * AST2 + bCol * 2;
    const uint32_t bLoB = bHiB + (XB_LO - XB_HI);

    float acc[2][8][4];
    #pragma unroll
    for (int mt = 0; mt < 2; mt++)
        #pragma unroll
        for (int nf = 0; nf < 8; nf++)
            #pragma unroll
            for (int r = 0; r < 4; r++) acc[mt][nf][r] = 0.0f;

    for (int c = 0; c < 4; c++) {
        const int kc = c * 64;
        #pragma unroll
        for (int i = 0; i < 8; i++) {
            int u = tid + i * 256;
            int m  = u >> 4;
            int c4 = u & 15;
            float4 v = *reinterpret_cast<const float4*>(
                X + ((size_t)m * Sdim + s) * Idim + kc + c4 * 4);
            uint2 uh, ul;
            split4(v, uh, ul);
            *reinterpret_cast<uint2*>(xsm + XA_HI + m * AST2 + c4 * 8) = uh;
            *reinterpret_cast<uint2*>(xsm + XA_LO + m * AST2 + c4 * 8) = ul;
        }
        #pragma unroll
        for (int i = 0; i < 8; i++) {
            int u = tid + i * 256;
            int n  = u >> 4;
            int c4 = u & 15;
            float4 v = *reinterpret_cast<const float4*>(
                W_ih + (size_t)(nb * 128 + n) * Idim + kc + c4 * 4);
            uint2 uh, ul;
            split4(v, uh, ul);
            *reinterpret_cast<uint2*>(xsm + XB_HI + n * AST2 + c4 * 8) = uh;
            *reinterpret_cast<uint2*>(xsm + XB_LO + n * AST2 + c4 * 8) = ul;
        }
        __syncthreads();

        #pragma unroll
        for (int kt = 0; kt < 4; kt++) {
            const uint32_t ko = (uint32_t)(kt * 32);
            uint32_t ah[2][4], al[2][4];
            LDSM4(ah[0], aHiB + ko);
            LDSM4(ah[1], aHiB + 16 * AST2 + ko);
            LDSM4(al[0], aLoB + ko);
            LDSM4(al[1], aLoB + 16 * AST2 + ko);
            #pragma unroll
            for (int np = 0; np < 4; np++) {
                uint32_t bh[4], bl[4];
                LDSM4(bh, bHiB + np * (16 * AST2) + ko);
                LDSM4(bl, bLoB + np * (16 * AST2) + ko);
                #pragma unroll
                for (int mt = 0; mt < 2; mt++) {
                    MMA_BF16(acc[mt][np * 2 + 0], ah[mt], bh + 0);
                    MMA_BF16(acc[mt][np * 2 + 0], ah[mt], bl + 0);
                    MMA_BF16(acc[mt][np * 2 + 0], al[mt], bh + 0);
                    MMA_BF16(acc[mt][np * 2 + 1], ah[mt], bh + 2);
                    MMA_BF16(acc[mt][np * 2 + 1], ah[mt], bl + 2);
                    MMA_BF16(acc[mt][np * 2 + 1], al[mt], bh + 2);
                }
            }
        }
        __syncthreads();
    }

    #pragma unroll
    for (int mt = 0; mt < 2; mt++) {
        const int row = wm + mt * 16 + (lid >> 2);
        #pragma unroll
        for (int nf = 0; nf < 8; nf++) {
            const int col = nb * 128 + wn + nf * 8 + (lid & 3) * 2;
            const float bb0 = __ldg(b_ih + col) + __ldg(b_hh + col);
            const float bb1 = __ldg(b_ih + col + 1) + __ldg(b_hh + col + 1);
            float* o = hs + ((size_t)s * Bdim + row) * Hdim + col;
            *reinterpret_cast<float2*>(o) =
                make_float2(acc[mt][nf][0] + bb0, acc[mt][nf][1] + bb1);
            *reinterpret_cast<float2*>(o + 8 * Hdim) =
                make_float2(acc[mt][nf][2] + bb0, acc[mt][nf][3] + bb1);
        }
    }
}

// ---------------------------------------------------------------------------
// Phase 2: persistent scan (R14 structure + release/acquire signaling,
// xp prefetch, float4 reduce, hs store off the critical path).
// ---------------------------------------------------------------------------
__global__ __launch_bounds__(256, 1) void rnn_scan_kernel(
    const float* __restrict__ hidden,
    const float* __restrict__ W_hh,
    const float* __restrict__ W_fc,
    const float* __restrict__ b_fc,
    float* __restrict__ out,
    float* __restrict__ hs,
    float* __restrict__ ss,
    float* __restrict__ sf)
{
    const int tid = threadIdx.x;
    const int wid = tid >> 5;
    const int lid = tid & 31;
    const int cta = blockIdx.x;
    const int nb  = cta >> 3;     // 0..15 N-block
    const int ks  = cta & 7;      // 0..7  K-split (= group id)
    const int k0  = ks * KBLK;

    // warp layout: 4(m) x 2(n)
    const int wr = wid & 3;
    const int wm = wr * 32;
    const int wn = (wid >> 2) * 32;

    // ---- one-time: hoist B (W_hh) fragments into registers (hi/lo) ----
    uint32_t bh[8][4][2], bl[8][4][2];
    #pragma unroll
    for (int kt = 0; kt < 8; kt++) {
        #pragma unroll
        for (int nt = 0; nt < 4; nt++) {
            int n_g = nb * NBLK + wn + nt * 8 + (lid >> 2);
            int k_g = k0 + kt * 16 + (lid & 3) * 2;
            const float* wp = W_hh + (size_t)n_g * Hdim + k_g;
            float2 w0 = *reinterpret_cast<const float2*>(wp);
            float2 w1 = *reinterpret_cast<const float2*>(wp + 8);
            split2(w0, bh[kt][nt][0], bl[kt][nt][0]);
            split2(w1, bh[kt][nt][1], bl[kt][nt][1]);
        }
    }

    // ---- one-time: stage h0 rows nb*8..+8 into gAf[ks] parity 0 ----
    #pragma unroll
    for (int e = 0; e < 2; e++) {
        int ph = tid * 2 + e;
        int rl = ph >> 6;
        int c  = (ph & 63) * 2;
        int row = nb * 8 + rl;
        float2 v = *reinterpret_cast<const float2*>(
            hidden + (size_t)row * Hdim + k0 + c);
        uint32_t uh, ul;
        split2(v, uh, ul);
        stage_pair(ks, 0, row, c, uh, ul);
    }

    // counter bases (monotonic; replay-safe)
    unsigned done_base = 0, gst_base = 0;
    if (tid == 0) {
        done_base = ldv(&g_done[ks * 32]);
        gst_base  = ldv(&g_gst[ks * 32]);
    }
    grid_barrier();

    // reduce-slice geometry (float4 per thread): rows nb*8..+8, cols k0..+128
    const int r_rl = tid >> 5;              // 0..7
    const int r_c  = (tid & 31) * 4;        // 0..124
    const size_t r_row = (size_t)(nb * 8 + r_rl);
    const size_t r_col = (size_t)k0 + r_c;

    for (int t = 0; t < Sdim; t++) {
        float* Pbuf = g_P + (size_t)(t & 1) * (NK * Bdim * Hdim);
        const uint32_t* afb = g_Af + (size_t)(t & 1) * AF_PAR + ks * AF_KS + lid * 4;

        // ---- wait staged (skipped at t=0; h0 covered by grid_barrier) ----
        if (t > 0) {
            if (tid == 0) {
                unsigned need = gst_base + 16u * (unsigned)t;
                while ((int)(ldrelax(&g_gst[ks * 32]) - need) < 0) { }
                fence_acq();
            }
            __syncthreads();
        }

        // ---- GEMM: A fragments via LDG.128, B from registers ----
        float acc[2][4][4];
        #pragma unroll
        for (int mt = 0; mt < 2; mt++)
            #pragma unroll
            for (int nt = 0; nt < 4; nt++)
                #pragma unroll
                for (int r = 0; r < 4; r++) acc[mt][nt][r] = 0.0f;

        uint32_t ah[2][2][4], al[2][2][4];
        {
            const uint32_t* fb = afb + (size_t)(wr * 8 + 0) * 512;
            LDCG128(ah[0][0], fb);
            LDCG128(ah[0][1], fb + 128);
            LDCG128(al[0][0], fb + 256);
            LDCG128(al[0][1], fb + 384);
        }
        #pragma unroll
        for (int kt = 0; kt < 8; kt++) {
            const int cur = kt & 1, nxt = cur ^ 1;
            if (kt < 7) {
                const uint32_t* fb = afb + (size_t)(wr * 8 + kt + 1) * 512;
                LDCG128(ah[nxt][0], fb);
                LDCG128(ah[nxt][1], fb + 128);
                LDCG128(al[nxt][0], fb + 256);
                LDCG128(al[nxt][1], fb + 384);
            }
            #pragma unroll
            for (int mt = 0; mt < 2; mt++) {
                #pragma unroll
                for (int nt = 0; nt < 4; nt++) {
                    MMA_BF16(acc[mt][nt], ah[cur][mt], bh[kt][nt]);
                    MMA_BF16(acc[mt][nt], ah[cur][mt], bl[kt][nt]);
                    MMA_BF16(acc[mt][nt], al[cur][mt], bh[kt][nt]);
                }
            }
        }

        // ---- store partials ----
        #pragma unroll
        for (int mt = 0; mt < 2; mt++) {
            #pragma unroll
            for (int nt = 0; nt < 4; nt++) {
                const int row = wm + mt * 16 + (lid >> 2);
                const int col = wn + nt * 8 + (lid & 3) * 2;
                float* p = Pbuf + ((size_t)ks * Bdim + row) * Hdim + nb * NBLK + col;
                *reinterpret_cast<float2*>(p) =
                    make_float2(acc[mt][nt][0], acc[mt][nt][1]);
                *reinterpret_cast<float2*>(p + 8 * Hdim) =
                    make_float2(acc[mt][nt][2], acc[mt][nt][3]);
            }
        }

        // ---- prefetch xp for the reduce (written by xproj; race-free) ----
        float* xp = hs + (size_t)t * Bdim * Hdim + r_row * Hdim + r_col;
        float4 sum = ldcg4(xp);

        // ---- signal gemm done for column-group nb>>1 (release) ----
        __syncthreads();
        if (tid == 0) {
            red_release(&g_done[(nb >> 1) * 32], 1u);
            unsigned need = done_base + 16u * (unsigned)(t + 1);
            while ((int)(ldrelax(&g_done[ks * 32]) - need) < 0) { }
            fence_acq();
        }
        __syncthreads();

        // ---- reduce rows nb*8..+8 x cols k0..+128; tanh; stage; signal; hs ----
        {
            #pragma unroll
            for (int q = 0; q < NK; q++) {
                float4 pv = ldcg4(Pbuf + ((size_t)q * Bdim + r_row) * Hdim + r_col);
                sum.x += pv.x; sum.y += pv.y; sum.z += pv.z; sum.w += pv.w;
            }
            float4 hv = make_float4(tanh_fast(sum.x), tanh_fast(sum.y),
                                    tanh_fast(sum.z), tanh_fast(sum.w));
            uint2 uh, ul;
            split4(hv, uh, ul);
            const int par = (t + 1) & 1;
            stage_pair(ks, par, (int)r_row, r_c,     uh.x, ul.x);
            stage_pair(ks, par, (int)r_row, r_c + 2, uh.y, ul.y);

            __syncthreads();
            if (tid == 0) red_release(&g_gst[ks * 32], 1u);

            // hs store off the critical path
            *reinterpret_cast<float4*>(xp) = hv;
        }
    }

    grid_barrier();   // all hs rows final before cross-row tail reads

    // ---- tail: state_start, state_final, fc output ----
    const float* hfin = hs + (size_t)(Sdim - 1) * Bdim * Hdim;
    {
        const size_t off = (size_t)cta * Hdim + tid * 4;
        *reinterpret_cast<float4*>(ss + off) = ldcg4(hs + off);
        *reinterpret_cast<float4*>(sf + off) = ldcg4(hfin + off);
    }
    if (cta < 16) {
        const int w = tid >> 5;
        const int lane = tid & 31;
        const int b = cta * 8 + w;
        float sum = 0.0f;
        #pragma unroll 8
        for (int h = lane; h < Hdim; h += 32)
            sum += __ldcg(hfin + (size_t)b * Hdim + h) * W_fc[h];
        #pragma unroll
        for (int o = 16; o > 0; o >>= 1)
            sum += __shfl_down_sync(0xffffffffu, sum, o);
        if (lane == 0) out[b] = sum + b_fc[0];
    }
}

extern "C" void kernel_launch(void* const* d_in, const int* in_sizes, int n_in,
                              void* d_out, int out_size) {
    (void)in_sizes; (void)n_in; (void)out_size;
    const float* X      = (const float*)d_in[0];
    const float* hidden = (const float*)d_in[1];
    const float* W_ih   = (const float*)d_in[2];
    const float* W_hh   = (const float*)d_in[3];
    const float* b_ih   = (const float*)d_in[4];
    const float* b_hh   = (const float*)d_in[5];
    const float* W_fc   = (const float*)d_in[6];
    const float* b_fc   = (const float*)d_in[7];

    float* out = (float*)d_out;                       // (B, 1)
    float* hs  = out + Bdim;                          // (S, B, H)
    float* ss  = hs + (size_t)Sdim * Bdim * Hdim;     // state_start (B,H)
    float* sf  = ss + (size_t)Bdim * Hdim;            // state_final (B,H)

    cudaFuncSetAttribute(xproj_kernel,
                         cudaFuncAttributeMaxDynamicSharedMemorySize, XSMEM_SZ);

    xproj_kernel<<<dim3(8, Sdim), 256, XSMEM_SZ>>>(X, W_ih, b_ih, b_hh, hs);
    rnn_scan_kernel<<<NCTA, 256>>>(hidden, W_hh, W_fc, b_fc, out, hs, ss, sf);
}

// round 17
// speedup vs baseline: 1.4259x; 1.4063x over previous
#include <cuda_runtime.h>
#include <cuda_bf16.h>
#include <cstdint>
#include <cstddef>

#define Bdim 128
#define Sdim 512
#define Idim 256
#define Hdim 1024
#define NCTA 128

// scan decomposition: 16 N-blocks x 8 K-splits = 128 CTAs
#define NK 8
#define NBLK 64    // N columns per CTA (scan)
#define KBLK 128   // K slice per CTA (scan)

// A-fragment staging buffer geometry (uint32 units)
// frag id fi = (wr*8 + kt)*4 + prec*2 + mt ; per ks: 4*8*4 = 128 frags x 128 uints
#define AF_KS  (128 * 128)
#define AF_PAR (8 * AF_KS)

// xproj smem: K-chunk 64, padded 144 B stride
#define AST2 144
#define XA_HI 0
#define XA_LO (XA_HI + 128 * AST2)
#define XB_HI (XA_LO + 128 * AST2)
#define XB_LO (XB_HI + 128 * AST2)
#define XSMEM_SZ (XB_LO + 128 * AST2)     // 73728 B

__device__ float g_P[2 * NK * Bdim * Hdim];       // double-buffered split-K partials (8 MB)
__device__ uint32_t g_Af[2 * AF_PAR];             // fragment-layout staged A (hi/lo pairs), 1 MB
__device__ unsigned g_grp[8 * 32];                // init/final grid barrier tree
__device__ unsigned g_root = 0;
__device__ unsigned g_gen = 0;
__device__ unsigned g_gcnt[8 * 32];               // group barriers (per ks)
__device__ unsigned g_ggen[8 * 32];
__device__ unsigned g_done[8 * 32];               // per-ks gemm-done counters (monotonic)

// ---------------------------------------------------------------------------
// helpers
// ---------------------------------------------------------------------------
__device__ __forceinline__ unsigned ldv(const unsigned* p) {
    unsigned v;
    asm volatile("ld.volatile.global.u32 %0, [%1];" : "=r"(v) : "l"(p));
    return v;
}
__device__ __forceinline__ float2 ldcg2(const float* p) {
    return __ldcg(reinterpret_cast<const float2*>(p));
}
__device__ __forceinline__ float4 ldcg4(const float* p) {
    return __ldcg(reinterpret_cast<const float4*>(p));
}
__device__ __forceinline__ uint32_t smem_u32(const void* p) {
    uint32_t a;
    asm("{ .reg .u64 t; cvta.to.shared.u64 t, %1; cvt.u32.u64 %0, t; }" : "=r"(a) : "l"(p));
    return a;
}

#define LDSM4(r, addr) \
    asm volatile("ldmatrix.sync.aligned.m8n8.x4.shared.b16 {%0,%1,%2,%3}, [%4];" \
        : "=r"((r)[0]), "=r"((r)[1]), "=r"((r)[2]), "=r"((r)[3]) : "r"(addr))

#define MMA_BF16(d, a, b) \
    asm volatile("mma.sync.aligned.m16n8k16.row.col.f32.bf16.bf16.f32 " \
        "{%0,%1,%2,%3}, {%4,%5,%6,%7}, {%8,%9}, {%0,%1,%2,%3};" \
        : "+f"((d)[0]), "+f"((d)[1]), "+f"((d)[2]), "+f"((d)[3]) \
        : "r"((a)[0]), "r"((a)[1]), "r"((a)[2]), "r"((a)[3]), \
          "r"((b)[0]), "r"((b)[1]))

#define LDCG128(r, p) do { \
    uint4 v_ = __ldcg(reinterpret_cast<const uint4*>(p)); \
    (r)[0] = v_.x; (r)[1] = v_.y; (r)[2] = v_.z; (r)[3] = v_.w; } while (0)

__device__ __forceinline__ void split4(float4 v, uint2& uh, uint2& ul) {
    __nv_bfloat16 h0 = __float2bfloat16(v.x);
    __nv_bfloat16 h1 = __float2bfloat16(v.y);
    __nv_bfloat16 h2 = __float2bfloat16(v.z);
    __nv_bfloat16 h3 = __float2bfloat16(v.w);
    __nv_bfloat16 l0 = __float2bfloat16(v.x - __bfloat162float(h0));
    __nv_bfloat16 l1 = __float2bfloat16(v.y - __bfloat162float(h1));
    __nv_bfloat16 l2 = __float2bfloat16(v.z - __bfloat162float(h2));
    __nv_bfloat16 l3 = __float2bfloat16(v.w - __bfloat162float(h3));
    uh.x = (uint32_t)__bfloat16_as_ushort(h0) | ((uint32_t)__bfloat16_as_ushort(h1) << 16);
    uh.y = (uint32_t)__bfloat16_as_ushort(h2) | ((uint32_t)__bfloat16_as_ushort(h3) << 16);
    ul.x = (uint32_t)__bfloat16_as_ushort(l0) | ((uint32_t)__bfloat16_as_ushort(l1) << 16);
    ul.y = (uint32_t)__bfloat16_as_ushort(l2) | ((uint32_t)__bfloat16_as_ushort(l3) << 16);
}
__device__ __forceinline__ void split2(float2 v, uint32_t& uh, uint32_t& ul) {
    __nv_bfloat16 h0 = __float2bfloat16(v.x);
    __nv_bfloat16 h1 = __float2bfloat16(v.y);
    __nv_bfloat16 l0 = __float2bfloat16(v.x - __bfloat162float(h0));
    __nv_bfloat16 l1 = __float2bfloat16(v.y - __bfloat162float(h1));
    uh = (uint32_t)__bfloat16_as_ushort(h0) | ((uint32_t)__bfloat16_as_ushort(h1) << 16);
    ul = (uint32_t)__bfloat16_as_ushort(l0) | ((uint32_t)__bfloat16_as_ushort(l1) << 16);
}

__device__ __forceinline__ float tanh_fast(float x) {
    float xc = fminf(fmaxf(x, -9.0f), 9.0f);
    float e = __expf(2.0f * xc);
    return __fdividef(e - 1.0f, e + 1.0f);
}

// Full-grid two-level tree barrier (init/final only; monotonic, replay-safe).
__device__ __forceinline__ void grid_barrier() {
    __threadfence();
    __syncthreads();
    if (threadIdx.x == 0) {
        unsigned my = ldv(&g_gen);
        unsigned o = atomicAdd(&g_grp[(blockIdx.x & 7) * 32], 1u);
        if ((o & 15u) == 15u) {
            unsigned r = atomicAdd(&g_root, 1u);
            if ((r & 7u) == 7u) atomicAdd(&g_gen, 1u);
        }
        while (ldv(&g_gen) == my) { }
    }
    __syncthreads();
}

// 16-CTA group barrier (group = ks).
__device__ __forceinline__ void group_barrier(int g) {
    __threadfence();
    __syncthreads();
    if (threadIdx.x == 0) {
        unsigned my = ldv(&g_ggen[g * 32]);
        unsigned o = atomicAdd(&g_gcnt[g * 32], 1u);
        if ((o & 15u) == 15u) atomicAdd(&g_ggen[g * 32], 1u);
        while (ldv(&g_ggen[g * 32]) == my) { }
    }
    __syncthreads();
}

// Write one (hi, lo) column-pair of h into the fragment-layout staging buffer.
// Mirrors the mma.sync m16n8k16 A-fragment mapping.
__device__ __forceinline__ void stage_pair(int ks, int par, int row, int c,
                                           uint32_t uh, uint32_t ul) {
    int wr = row >> 5;
    int mt = (row >> 4) & 1;
    int fr = row & 15;
    int kt = c >> 4;
    int fk = c & 15;
    int p  = (fr >> 3) + ((fk >> 3) << 1);
    int lane = (fr & 7) * 4 + ((fk & 7) >> 1);
    int fiH = (wr * 8 + kt) * 4 + mt;        // prec 0
    uint32_t* b = g_Af + (size_t)par * AF_PAR + ks * AF_KS + lane * 4 + p;
    b[(size_t)fiH * 128]       = uh;
    b[(size_t)(fiH + 2) * 128] = ul;          // prec 1
}

// ---------------------------------------------------------------------------
// Phase 1: x_proj via bf16 hi/lo mma.sync (unchanged — known good)
// ---------------------------------------------------------------------------
__global__ __launch_bounds__(256) void xproj_kernel(
    const float* __restrict__ X,
    const float* __restrict__ W_ih,
    const float* __restrict__ b_ih,
    const float* __restrict__ b_hh,
    float* __restrict__ hs)
{
    extern __shared__ char xsm[];
    const uint32_t sbase = smem_u32(xsm);
    const int nb = blockIdx.x;
    const int s  = blockIdx.y;
    const int tid = threadIdx.x;
    const int wid = tid >> 5;
    const int lid = tid & 31;

    const int wm = (wid & 3) * 32;
    const int wn = (wid >> 2) * 64;

    const uint32_t aRow = (uint32_t)(wm + (lid & 15));
    const uint32_t aCol = (uint32_t)((lid >> 4) * 8);
    const uint32_t aHiB = sbase + XA_HI + aRow * AST2 + aCol * 2;
    const uint32_t aLoB = aHiB + (XA_LO - XA_HI);
    const uint32_t bRow = (uint32_t)(wn + ((lid >> 4) << 3) + (lid & 7));
    const uint32_t bCol = (uint32_t)(((lid >> 3) & 1) * 8);
    const uint32_t bHiB = sbase + XB_HI + bRow * AST2 + bCol * 2;
    const uint32_t bLoB = bHiB + (XB_LO - XB_HI);

    float acc[2][8][4];
    #pragma unroll
    for (int mt = 0; mt < 2; mt++)
        #pragma unroll
        for (int nf = 0; nf < 8; nf++)
            #pragma unroll
            for (int r = 0; r < 4; r++) acc[mt][nf][r] = 0.0f;

    for (int c = 0; c < 4; c++) {
        const int kc = c * 64;
        #pragma unroll
        for (int i = 0; i < 8; i++) {
            int u = tid + i * 256;
            int m  = u >> 4;
            int c4 = u & 15;
            float4 v = *reinterpret_cast<const float4*>(
                X + ((size_t)m * Sdim + s) * Idim + kc + c4 * 4);
            uint2 uh, ul;
            split4(v, uh, ul);
            *reinterpret_cast<uint2*>(xsm + XA_HI + m * AST2 + c4 * 8) = uh;
            *reinterpret_cast<uint2*>(xsm + XA_LO + m * AST2 + c4 * 8) = ul;
        }
        #pragma unroll
        for (int i = 0; i < 8; i++) {
            int u = tid + i * 256;
            int n  = u >> 4;
            int c4 = u & 15;
            float4 v = *reinterpret_cast<const float4*>(
                W_ih + (size_t)(nb * 128 + n) * Idim + kc + c4 * 4);
            uint2 uh, ul;
            split4(v, uh, ul);
            *reinterpret_cast<uint2*>(xsm + XB_HI + n * AST2 + c4 * 8) = uh;
            *reinterpret_cast<uint2*>(xsm + XB_LO + n * AST2 + c4 * 8) = ul;
        }
        __syncthreads();

        #pragma unroll
        for (int kt = 0; kt < 4; kt++) {
            const uint32_t ko = (uint32_t)(kt * 32);
            uint32_t ah[2][4], al[2][4];
            LDSM4(ah[0], aHiB + ko);
            LDSM4(ah[1], aHiB + 16 * AST2 + ko);
            LDSM4(al[0], aLoB + ko);
            LDSM4(al[1], aLoB + 16 * AST2 + ko);
            #pragma unroll
            for (int np = 0; np < 4; np++) {
                uint32_t bh[4], bl[4];
                LDSM4(bh, bHiB + np * (16 * AST2) + ko);
                LDSM4(bl, bLoB + np * (16 * AST2) + ko);
                #pragma unroll
                for (int mt = 0; mt < 2; mt++) {
                    MMA_BF16(acc[mt][np * 2 + 0], ah[mt], bh + 0);
                    MMA_BF16(acc[mt][np * 2 + 0], ah[mt], bl + 0);
                    MMA_BF16(acc[mt][np * 2 + 0], al[mt], bh + 0);
                    MMA_BF16(acc[mt][np * 2 + 1], ah[mt], bh + 2);
                    MMA_BF16(acc[mt][np * 2 + 1], ah[mt], bl + 2);
                    MMA_BF16(acc[mt][np * 2 + 1], al[mt], bh + 2);
                }
            }
        }
        __syncthreads();
    }

    #pragma unroll
    for (int mt = 0; mt < 2; mt++) {
        const int row = wm + mt * 16 + (lid >> 2);
        #pragma unroll
        for (int nf = 0; nf < 8; nf++) {
            const int col = nb * 128 + wn + nf * 8 + (lid & 3) * 2;
            const float bb0 = __ldg(b_ih + col) + __ldg(b_hh + col);
            const float bb1 = __ldg(b_ih + col + 1) + __ldg(b_hh + col + 1);
            float* o = hs + ((size_t)s * Bdim + row) * Hdim + col;
            *reinterpret_cast<float2*>(o) =
                make_float2(acc[mt][nf][0] + bb0, acc[mt][nf][1] + bb1);
            *reinterpret_cast<float2*>(o + 8 * Hdim) =
                make_float2(acc[mt][nf][2] + bb0, acc[mt][nf][3] + bb1);
        }
    }
}

// ---------------------------------------------------------------------------
// Phase 2: persistent scan (R14 structure verbatim; only the reduce phase
// is changed: float4 gather + hs store after staging).
// ---------------------------------------------------------------------------
__global__ __launch_bounds__(256, 1) void rnn_scan_kernel(
    const float* __restrict__ hidden,
    const float* __restrict__ W_hh,
    const float* __restrict__ W_fc,
    const float* __restrict__ b_fc,
    float* __restrict__ out,
    float* __restrict__ hs,
    float* __restrict__ ss,
    float* __restrict__ sf)
{
    const int tid = threadIdx.x;
    const int wid = tid >> 5;
    const int lid = tid & 31;
    const int cta = blockIdx.x;
    const int nb  = cta >> 3;     // 0..15 N-block
    const int ks  = cta & 7;      // 0..7  K-split (= group id)
    const int k0  = ks * KBLK;

    // warp layout: 4(m) x 2(n)
    const int wr = wid & 3;          // m-row: rows wr*32..+31
    const int wm = wr * 32;
    const int wn = (wid >> 2) * 32;  // n-half: cols wn..wn+31 (of CTA's n64)

    // ---- one-time: hoist B (W_hh) fragments into registers (hi/lo) ----
    uint32_t bh[8][4][2], bl[8][4][2];
    #pragma unroll
    for (int kt = 0; kt < 8; kt++) {
        #pragma unroll
        for (int nt = 0; nt < 4; nt++) {
            int n_g = nb * NBLK + wn + nt * 8 + (lid >> 2);
            int k_g = k0 + kt * 16 + (lid & 3) * 2;
            const float* wp = W_hh + (size_t)n_g * Hdim + k_g;
            float2 w0 = *reinterpret_cast<const float2*>(wp);
            float2 w1 = *reinterpret_cast<const float2*>(wp + 8);
            split2(w0, bh[kt][nt][0], bl[kt][nt][0]);
            split2(w1, bh[kt][nt][1], bl[kt][nt][1]);
        }
    }

    // ---- one-time: stage h0 rows nb*8..+8 into gAf[ks] parity 0 ----
    #pragma unroll
    for (int e = 0; e < 2; e++) {
        int ph = tid * 2 + e;            // 0..511
        int rl = ph >> 6;                // 0..7
        int c  = (ph & 63) * 2;          // 0..126
        int row = nb * 8 + rl;
        float2 v = *reinterpret_cast<const float2*>(
            hidden + (size_t)row * Hdim + k0 + c);
        uint32_t uh, ul;
        split2(v, uh, ul);
        stage_pair(ks, 0, row, c, uh, ul);
    }

    // read done-counter base (before anyone signals), then align whole grid
    unsigned done_base = 0;
    if (tid == 0) done_base = ldv(&g_done[ks * 32]);
    grid_barrier();

    // reduce-slice geometry (float4 per thread): rows nb*8..+8, cols k0..+128
    const int r_rl = tid >> 5;              // 0..7
    const int r_c  = (tid & 31) * 4;        // 0..124
    const int r_row = nb * 8 + r_rl;
    const size_t r_colH = (size_t)k0 + r_c;

    for (int t = 0; t < Sdim; t++) {
        float* Pbuf = g_P + (size_t)(t & 1) * (NK * Bdim * Hdim);
        const uint32_t* afb = g_Af + (size_t)(t & 1) * AF_PAR + ks * AF_KS + lid * 4;

        // ---- GEMM: A fragments via LDG.128, B from registers ----
        float acc[2][4][4];
        #pragma unroll
        for (int mt = 0; mt < 2; mt++)
            #pragma unroll
            for (int nt = 0; nt < 4; nt++)
                #pragma unroll
                for (int r = 0; r < 4; r++) acc[mt][nt][r] = 0.0f;

        uint32_t ah[2][2][4], al[2][2][4];   // [buf][mt][4]
        {
            const uint32_t* fb = afb + (size_t)(wr * 8 + 0) * 512;
            LDCG128(ah[0][0], fb);
            LDCG128(ah[0][1], fb + 128);
            LDCG128(al[0][0], fb + 256);
            LDCG128(al[0][1], fb + 384);
        }
        #pragma unroll
        for (int kt = 0; kt < 8; kt++) {
            const int cur = kt & 1, nxt = cur ^ 1;
            if (kt < 7) {
                const uint32_t* fb = afb + (size_t)(wr * 8 + kt + 1) * 512;
                LDCG128(ah[nxt][0], fb);
                LDCG128(ah[nxt][1], fb + 128);
                LDCG128(al[nxt][0], fb + 256);
                LDCG128(al[nxt][1], fb + 384);
            }
            #pragma unroll
            for (int mt = 0; mt < 2; mt++) {
                #pragma unroll
                for (int nt = 0; nt < 4; nt++) {
                    MMA_BF16(acc[mt][nt], ah[cur][mt], bh[kt][nt]);
                    MMA_BF16(acc[mt][nt], ah[cur][mt], bl[kt][nt]);
                    MMA_BF16(acc[mt][nt], al[cur][mt], bh[kt][nt]);
                }
            }
        }

        // ---- store partials ----
        #pragma unroll
        for (int mt = 0; mt < 2; mt++) {
            #pragma unroll
            for (int nt = 0; nt < 4; nt++) {
                const int row = wm + mt * 16 + (lid >> 2);
                const int col = wn + nt * 8 + (lid & 3) * 2;
                float* p = Pbuf + ((size_t)ks * Bdim + row) * Hdim + nb * NBLK + col;
                *reinterpret_cast<float2*>(p) =
                    make_float2(acc[mt][nt][0], acc[mt][nt][1]);
                *reinterpret_cast<float2*>(p + 8 * Hdim) =
                    make_float2(acc[mt][nt][2], acc[mt][nt][3]);
            }
        }

        // ---- signal gemm done for column-group nb>>1 ----
        __threadfence();
        __syncthreads();
        if (tid == 0) {
            atomicAdd(&g_done[(nb >> 1) * 32], 1u);
            // wait for the 16 producers of our reduce slice
            while (ldv(&g_done[ks * 32]) - done_base < 16u * (unsigned)(t + 1)) { }
        }
        __syncthreads();

        // ---- reduce rows nb*8..+8 x cols ks*128..+128 (float4/thread) ----
        {
            const int par = (t + 1) & 1;
            float* xp = hs + (size_t)t * Bdim * Hdim + (size_t)r_row * Hdim + r_colH;
            float4 sum = *reinterpret_cast<const float4*>(xp);
            #pragma unroll
            for (int q = 0; q < NK; q++) {
                float4 pv = ldcg4(Pbuf + ((size_t)q * Bdim + r_row) * Hdim + r_colH);
                sum.x += pv.x; sum.y += pv.y; sum.z += pv.z; sum.w += pv.w;
            }
            float4 hv = make_float4(tanh_fast(sum.x), tanh_fast(sum.y),
                                    tanh_fast(sum.z), tanh_fast(sum.w));
            uint2 uh, ul;
            split4(hv, uh, ul);
            stage_pair(ks, par, r_row, r_c,     uh.x, ul.x);
            stage_pair(ks, par, r_row, r_c + 2, uh.y, ul.y);
            // hs store after staging (group_barrier's fence orders it)
            *reinterpret_cast<float4*>(xp) = hv;
        }

        group_barrier(ks);
    }

    grid_barrier();   // all hs rows final before cross-row tail reads

    // ---- tail: state_start, state_final, fc output ----
    const float* hfin = hs + (size_t)(Sdim - 1) * Bdim * Hdim;
    {
        const size_t off = (size_t)cta * Hdim + tid * 4;
        *reinterpret_cast<float4*>(ss + off) = ldcg4(hs + off);
        *reinterpret_cast<float4*>(sf + off) = ldcg4(hfin + off);
    }
    if (cta < 16) {
        const int w = tid >> 5;
        const int lane = tid & 31;
        const int b = cta * 8 + w;
        float sum = 0.0f;
        #pragma unroll 8
        for (int h = lane; h < Hdim; h += 32)
            sum += __ldcg(hfin + (size_t)b * Hdim + h) * W_fc[h];
        #pragma unroll
        for (int o = 16; o > 0; o >>= 1)
            sum += __shfl_down_sync(0xffffffffu, sum, o);
        if (lane == 0) out[b] = sum + b_fc[0];
    }
}

extern "C" void kernel_launch(void* const* d_in, const int* in_sizes, int n_in,
                              void* d_out, int out_size) {
    (void)in_sizes; (void)n_in; (void)out_size;
    const float* X      = (const float*)d_in[0];
    const float* hidden = (const float*)d_in[1];
    const float* W_ih   = (const float*)d_in[2];
    const float* W_hh   = (const float*)d_in[3];
    const float* b_ih   = (const float*)d_in[4];
    const float* b_hh   = (const float*)d_in[5];
    const float* W_fc   = (const float*)d_in[6];
    const float* b_fc   = (const float*)d_in[7];

    float* out = (float*)d_out;                       // (B, 1)
    float* hs  = out + Bdim;                          // (S, B, H)
    float* ss  = hs + (size_t)Sdim * Bdim * Hdim;     // state_start (B,H)
    float* sf  = ss + (size_t)Bdim * Hdim;            // state_final (B,H)

    cudaFuncSetAttribute(xproj_kernel,
                         cudaFuncAttributeMaxDynamicSharedMemorySize, XSMEM_SZ);

    xproj_kernel<<<dim3(8, Sdim), 256, XSMEM_SZ>>>(X, W_ih, b_ih, b_hh, hs);
    rnn_scan_kernel<<<NCTA, 256>>>(hidden, W_hh, W_fc, b_fc, out, hs, ss, sf);
}